// round 1
// baseline (speedup 1.0000x reference)
#include <cuda_runtime.h>
#include <cuda_bf16.h>

// Problem constants
#define NN   32
#define CC   512
#define HWL  3136        // 56*56
#define GG   8
#define LL   64
#define MTOT 100352      // NN*HWL
#define EPSV 1e-4f
#define NPART 128        // 32 n-chunks * 4 k-chunks

// ---------------- scratch (device globals; no allocation allowed) -------------
__device__ float g_pcov[GG][NPART][LL * LL];  // partial Grams (16.8 MB)
__device__ float g_psum[GG][NPART][LL];       // partial channel sums
__device__ float g_mu[CC];
__device__ float g_cov[GG * LL * LL];
__device__ float g_subT[GG * LL * LL];        // whitening subspace, TRANSPOSED [g][j][i]
__device__ float g_t[CC];                     // t[c] = sum_j S[c'][j] * mu[g*64+j]

// =============================================================================
// Kernel 1: partial Gram + partial channel sums.
// grid (4 k-chunks, 32 n, 8 g), 256 threads. Symmetric: only upper 4x4 tiles.
// =============================================================================
__global__ __launch_bounds__(256) void k_cov_partial(const float* __restrict__ x) {
    const int q = blockIdx.x;           // k-chunk 0..3
    const int n = blockIdx.y;
    const int g = blockIdx.z;
    __shared__ float4 Xs[64][17];       // [channel][k4], padded to kill conflicts

    const int tid = threadIdx.x;

    // triangular tile map: tid < 136 -> (ty, tx) with tx >= ty, 16x16 tile grid
    int ty = -1, tx = -1;
    if (tid < 136) {
        int t = tid, r = 0;
        while (t >= 16 - r) { t -= 16 - r; ++r; }
        ty = r; tx = r + t;
    }

    const int tiles = (q == 0) ? 13 : 12;
    const int k0    = (q == 0) ? 0 : (832 + (q - 1) * 768);
    const float* base = x + ((size_t)n * CC + (size_t)g * LL) * HWL + k0;

    float acc[4][4] = {};
    float rowsum = 0.f;

    for (int tI = 0; tI < tiles; ++tI) {
        __syncthreads();
        // load 64 rows x 16 float4 (each row contiguous in gmem)
        #pragma unroll
        for (int idx = tid; idx < 1024; idx += 256) {
            int r = idx >> 4, c = idx & 15;
            Xs[r][c] = *reinterpret_cast<const float4*>(base + (size_t)r * HWL + tI * 64 + c * 4);
        }
        __syncthreads();

        if (tid < 64) {
            #pragma unroll
            for (int c = 0; c < 16; ++c) {
                float4 v = Xs[tid][c];
                rowsum += v.x + v.y + v.z + v.w;
            }
        }
        if (tid < 136) {
            #pragma unroll
            for (int c = 0; c < 16; ++c) {
                float4 a[4], b[4];
                #pragma unroll
                for (int u = 0; u < 4; ++u) a[u] = Xs[4 * ty + u][c];
                #pragma unroll
                for (int u = 0; u < 4; ++u) b[u] = Xs[4 * tx + u][c];
                #pragma unroll
                for (int u = 0; u < 4; ++u)
                    #pragma unroll
                    for (int w = 0; w < 4; ++w)
                        acc[u][w] = fmaf(a[u].x, b[w].x,
                                    fmaf(a[u].y, b[w].y,
                                    fmaf(a[u].z, b[w].z,
                                    fmaf(a[u].w, b[w].w, acc[u][w]))));
            }
        }
    }

    const int p = n * 4 + q;
    if (tid < 64) g_psum[g][p][tid] = rowsum;
    if (tid < 136) {
        float* out = &g_pcov[g][p][0];
        #pragma unroll
        for (int u = 0; u < 4; ++u)
            #pragma unroll
            for (int w = 0; w < 4; ++w) {
                int i = 4 * ty + u, j = 4 * tx + w;
                out[i * 64 + j] = acc[u][w];
                if (ty != tx) out[j * 64 + i] = acc[u][w];
            }
    }
}

// =============================================================================
// Kernel 2a: reduce channel sums -> mu.  grid 8, 64 threads.
// =============================================================================
__global__ __launch_bounds__(64) void k_mean() {
    const int g = blockIdx.x, i = threadIdx.x;
    float s = 0.f;
    #pragma unroll 4
    for (int p = 0; p < NPART; ++p) s += g_psum[g][p][i];
    g_mu[g * LL + i] = s / (float)MTOT;
}

// =============================================================================
// Kernel 2b: reduce partial Grams -> cov (with -mu mu^T + eps I). grid (16,8).
// =============================================================================
__global__ __launch_bounds__(256) void k_cov_finalize() {
    const int g = blockIdx.y;
    const int e = blockIdx.x * 256 + threadIdx.x;     // 0..4095
    const int i = e >> 6, j = e & 63;
    float s0 = 0.f, s1 = 0.f, s2 = 0.f, s3 = 0.f;
    #pragma unroll 4
    for (int p = 0; p < NPART; p += 4) {
        s0 += g_pcov[g][p + 0][e];
        s1 += g_pcov[g][p + 1][e];
        s2 += g_pcov[g][p + 2][e];
        s3 += g_pcov[g][p + 3][e];
    }
    float c = ((s0 + s1) + (s2 + s3)) / (float)MTOT - g_mu[g * LL + i] * g_mu[g * LL + j];
    if (i == j) c += EPSV;
    g_cov[g * LL * LL + e] = c;
}

// =============================================================================
// Kernel 3: power iteration + deflation. 8 blocks (one per group), 64 threads.
// Thread i owns row i of A and of the subspace S (in registers).
// Break condition matches reference: (j>0) && (lam_prev < lam || lam < eps).
// All reductions computed redundantly by every thread in a fixed order
// -> uniform branch decisions, bitwise deterministic.
// =============================================================================
#define MATVEC64(res, Aarr, vptr) {                                        \
    float y0 = 0.f, y1 = 0.f, y2 = 0.f, y3 = 0.f;                          \
    _Pragma("unroll")                                                      \
    for (int j_ = 0; j_ < 64; j_ += 4) {                                   \
        y0 = fmaf(Aarr[j_ + 0], (vptr)[j_ + 0], y0);                       \
        y1 = fmaf(Aarr[j_ + 1], (vptr)[j_ + 1], y1);                       \
        y2 = fmaf(Aarr[j_ + 2], (vptr)[j_ + 2], y2);                       \
        y3 = fmaf(Aarr[j_ + 3], (vptr)[j_ + 3], y3);                       \
    }                                                                      \
    res = (y0 + y1) + (y2 + y3);                                           \
}

__device__ __forceinline__ float sumsq64(const float* v) {
    float y0 = 0.f, y1 = 0.f, y2 = 0.f, y3 = 0.f;
    #pragma unroll
    for (int j = 0; j < 64; j += 4) {
        y0 = fmaf(v[j + 0], v[j + 0], y0);
        y1 = fmaf(v[j + 1], v[j + 1], y1);
        y2 = fmaf(v[j + 2], v[j + 2], y2);
        y3 = fmaf(v[j + 3], v[j + 3], y3);
    }
    return (y0 + y1) + (y2 + y3);
}

__device__ __forceinline__ float dot64(const float* a, const float* b) {
    float y0 = 0.f, y1 = 0.f, y2 = 0.f, y3 = 0.f;
    #pragma unroll
    for (int j = 0; j < 64; j += 4) {
        y0 = fmaf(a[j + 0], b[j + 0], y0);
        y1 = fmaf(a[j + 1], b[j + 1], y1);
        y2 = fmaf(a[j + 2], b[j + 2], y2);
        y3 = fmaf(a[j + 3], b[j + 3], y3);
    }
    return (y0 + y1) + (y2 + y3);
}

__global__ __launch_bounds__(64) void k_pi(const float* __restrict__ vinit) {
    const int g = blockIdx.x, i = threadIdx.x;
    __shared__ float vs[2][64];
    __shared__ float av[64];

    float A[64], S[64];
    #pragma unroll
    for (int j = 0; j < 64; ++j) {
        A[j] = g_cov[g * LL * LL + i * 64 + j];
        S[j] = 0.f;
    }

    float lam_prev = 0.f;

    for (int e = 0; e < 64; ++e) {
        __syncthreads();                                   // protect vs from prior step readers
        vs[0][i] = vinit[((size_t)g * LL + e) * LL + i];   // raw v0 (row e)
        __syncthreads();

        float n2  = sumsq64(vs[0]);
        float inv = 1.f / (sqrtf(n2) + 1e-12f);            // normalization of v0, folded in
        int cur = 0;

        #pragma unroll 1
        for (int it = 0; it < 19; ++it) {
            float y;
            MATVEC64(y, A, vs[cur]);
            y *= inv;                                      // apply previous step's normalization
            vs[cur ^ 1][i] = y;
            __syncthreads();
            cur ^= 1;
            n2  = sumsq64(vs[cur]);
            inv = 1.f / (sqrtf(n2) + 1e-12f);
        }

        // final normalized v
        float vi = vs[cur][i] * inv;
        __syncthreads();
        vs[cur ^ 1][i] = vi;
        __syncthreads();
        cur ^= 1;

        float Avi;
        MATVEC64(Avi, A, vs[cur]);
        av[i] = Avi;
        __syncthreads();

        float vAv = dot64(vs[cur], av);
        float vv  = sumsq64(vs[cur]);
        float lam = vAv / vv;

        if (e > 0 && (lam_prev < lam || lam < EPSV)) break;  // uniform across block

        float svi = rsqrtf(lam) * vi;
        #pragma unroll
        for (int j = 0; j < 64; ++j) {
            float vj = vs[cur][j];
            S[j] = fmaf(svi, vj, S[j]);     // subspace += rsqrt(lam) * v v^T
            A[j] = fmaf(-Avi, vj, A[j]);    // A -= (A v) v^T
        }
        lam_prev = lam;
    }

    // store subspace transposed: g_subT[g][j][i] = S[i][j]
    #pragma unroll
    for (int j = 0; j < 64; ++j) g_subT[g * LL * LL + j * 64 + i] = S[j];

    // t[i] = sum_j S[i][j] * mu[g*64+j]
    float t = 0.f;
    #pragma unroll
    for (int j = 0; j < 64; ++j) t = fmaf(S[j], g_mu[g * LL + j], t);
    g_t[g * LL + i] = t;
}

// =============================================================================
// Kernel 4: apply whitening + affine.  out = (S @ x - t) * weight + bias.
// grid (49 hw-tiles, 32 n, 8 g), 256 threads, 64x64 output tile, K=64.
// =============================================================================
__global__ __launch_bounds__(256) void k_apply(const float* __restrict__ x,
                                               const float* __restrict__ wgt,
                                               const float* __restrict__ bia,
                                               float* __restrict__ out) {
    const int hb = blockIdx.x;   // hw tile (64 wide), 49 exact
    const int n  = blockIdx.y;
    const int g  = blockIdx.z;

    __shared__ float4 Xt[64][17];   // [j][m4]  x tile
    __shared__ float4 St[64][17];   // [k][i4]  S^T tile

    const int tid = threadIdx.x;
    const int ty = tid >> 4, tx = tid & 15;

    // load S^T (already stored transposed -> coalesced float4 loads)
    const float* subT = g_subT + g * LL * LL;
    #pragma unroll
    for (int idx = tid; idx < 1024; idx += 256) {
        int j = idx >> 4, i4 = idx & 15;
        St[j][i4] = *reinterpret_cast<const float4*>(subT + j * 64 + i4 * 4);
    }
    // load x tile: 64 channels x 64 hw
    const float* base = x + ((size_t)n * CC + (size_t)g * LL) * HWL + hb * 64;
    #pragma unroll
    for (int idx = tid; idx < 1024; idx += 256) {
        int j = idx >> 4, m4 = idx & 15;
        Xt[j][m4] = *reinterpret_cast<const float4*>(base + (size_t)j * HWL + m4 * 4);
    }
    __syncthreads();

    float acc[4][4] = {};
    #pragma unroll
    for (int k = 0; k < 64; ++k) {
        float4 a = St[k][ty];   // S[4ty..4ty+3][k]
        float4 b = Xt[k][tx];   // X[k][4tx..4tx+3]
        acc[0][0] = fmaf(a.x, b.x, acc[0][0]);
        acc[0][1] = fmaf(a.x, b.y, acc[0][1]);
        acc[0][2] = fmaf(a.x, b.z, acc[0][2]);
        acc[0][3] = fmaf(a.x, b.w, acc[0][3]);
        acc[1][0] = fmaf(a.y, b.x, acc[1][0]);
        acc[1][1] = fmaf(a.y, b.y, acc[1][1]);
        acc[1][2] = fmaf(a.y, b.z, acc[1][2]);
        acc[1][3] = fmaf(a.y, b.w, acc[1][3]);
        acc[2][0] = fmaf(a.z, b.x, acc[2][0]);
        acc[2][1] = fmaf(a.z, b.y, acc[2][1]);
        acc[2][2] = fmaf(a.z, b.z, acc[2][2]);
        acc[2][3] = fmaf(a.z, b.w, acc[2][3]);
        acc[3][0] = fmaf(a.w, b.x, acc[3][0]);
        acc[3][1] = fmaf(a.w, b.y, acc[3][1]);
        acc[3][2] = fmaf(a.w, b.z, acc[3][2]);
        acc[3][3] = fmaf(a.w, b.w, acc[3][3]);
    }

    // epilogue: (acc - t) * w + b, vectorized stores
    #pragma unroll
    for (int u = 0; u < 4; ++u) {
        int c = g * LL + 4 * ty + u;
        float tt = g_t[c], ww = wgt[c], bb = bia[c];
        float4 r;
        r.x = fmaf(acc[u][0] - tt, ww, bb);
        r.y = fmaf(acc[u][1] - tt, ww, bb);
        r.z = fmaf(acc[u][2] - tt, ww, bb);
        r.w = fmaf(acc[u][3] - tt, ww, bb);
        *reinterpret_cast<float4*>(out + ((size_t)n * CC + c) * HWL + hb * 64 + 4 * tx) = r;
    }
}

// =============================================================================
extern "C" void kernel_launch(void* const* d_in, const int* in_sizes, int n_in,
                              void* d_out, int out_size) {
    const float* x     = (const float*)d_in[0];
    const float* vinit = (const float*)d_in[1];
    const float* wgt   = (const float*)d_in[2];
    const float* bia   = (const float*)d_in[3];
    float* out = (float*)d_out;
    (void)in_sizes; (void)n_in; (void)out_size;

    k_cov_partial<<<dim3(4, 32, 8), 256>>>(x);
    k_mean<<<8, 64>>>();
    k_cov_finalize<<<dim3(16, 8), 256>>>();
    k_pi<<<8, 64>>>(vinit);
    k_apply<<<dim3(49, 32, 8), 256>>>(x, wgt, bia, out);
}